// round 16
// baseline (speedup 1.0000x reference)
#include <cuda_runtime.h>
#include <cuda_fp16.h>
#include <cstdint>

// Problem constants (fixed by reference)
#define NN   100000
#define EE   1600000
#define FH   128      // F_IN == H == HG
#define H3   384      // 3*HG
#define CC   40
#define LL   3

// ---------------- scratch (device globals; no allocation allowed) ----------
__device__ float g_xh1[(size_t)NN * FH];
__device__ float g_xh2[(size_t)NN * FH];
__device__ float4 g_xwh[(size_t)NN * FH / 8];   // fp16 xw, 16B-aligned
__device__ float g_h [(size_t)NN * FH];
__device__ float g_deg [NN];
__device__ float g_dinv[NN];
// CSR (dst-sorted edge list, rebuilt every call)
__device__ int   g_cnt[NN];          // histogram, then cursor
__device__ int   g_rowstart[NN + 1];
__device__ int   g_blocksum[256];
__device__ int   g_esrc[EE];
__device__ float g_ew2[EE];

#define SCAN_B 512
#define NBLK ((NN + SCAN_B - 1) / SCAN_B)   // 196

// ---------------- degree + histogram ----------------
__global__ void init_deg_kernel() {
    int i = blockIdx.x * blockDim.x + threadIdx.x;
    if (i < NN) { g_deg[i] = 1.0f; g_cnt[i] = 0; }   // self-loop weight 1
}

__global__ void accum_deg_kernel(const int* __restrict__ dst,
                                 const float* __restrict__ ew) {
    int e = blockIdx.x * blockDim.x + threadIdx.x;
    if (e < EE) {
        int d = dst[e];
        atomicAdd(&g_deg[d], ew[e]);
        atomicAdd(&g_cnt[d], 1);
    }
}

// ---------------- exclusive scan over g_cnt -> g_rowstart ----------------
__global__ void scan1_kernel() {
    __shared__ int sh[SCAN_B];
    int b = blockIdx.x, t = threadIdx.x;
    int i = b * SCAN_B + t;
    int v = (i < NN) ? g_cnt[i] : 0;
    sh[t] = v;
    __syncthreads();
    #pragma unroll
    for (int off = 1; off < SCAN_B; off <<= 1) {
        int x = (t >= off) ? sh[t - off] : 0;
        __syncthreads();
        sh[t] += x;
        __syncthreads();
    }
    if (i < NN) g_rowstart[i] = sh[t] - v;            // block-local exclusive
    if (t == SCAN_B - 1) g_blocksum[b] = sh[t];       // block total
}

__global__ void scan2_kernel() {
    __shared__ int sh[256];
    int t = threadIdx.x;   // 256 threads, NBLK=196
    int v = (t < NBLK) ? g_blocksum[t] : 0;
    sh[t] = v;
    __syncthreads();
    #pragma unroll
    for (int off = 1; off < 256; off <<= 1) {
        int x = (t >= off) ? sh[t - off] : 0;
        __syncthreads();
        sh[t] += x;
        __syncthreads();
    }
    if (t < NBLK) g_blocksum[t] = sh[t] - v;          // exclusive
}

__global__ void scan3_kernel() {     // also finalizes dinv
    int i = blockIdx.x * blockDim.x + threadIdx.x;
    if (i < NN) {
        int v = g_rowstart[i] + g_blocksum[i / SCAN_B];
        g_rowstart[i] = v;
        g_cnt[i] = v;      // cursor for fill
        g_dinv[i] = rsqrtf(g_deg[i]);   // deg >= 1 always
    }
    if (i == 0) g_rowstart[NN] = EE;
}

// ---------------- fill CSR: src + precomputed norm ----------------
__global__ void fill_kernel(const int* __restrict__ src,
                            const int* __restrict__ dst,
                            const float* __restrict__ ew) {
    int e = blockIdx.x * blockDim.x + threadIdx.x;
    if (e >= EE) return;
    int s = src[e], d = dst[e];
    int pos = atomicAdd(&g_cnt[d], 1);
    g_esrc[pos] = s;
    g_ew2[pos] = g_dinv[s] * ew[e] * g_dinv[d];
}

// ---------------- gather aggregation: warp per dst node, fp16 xw ---------
__device__ __forceinline__ void acc_half4(float4& acc, uint2 u, float w) {
    float2 f0 = __half22float2(*(__half2*)&u.x);
    float2 f1 = __half22float2(*(__half2*)&u.y);
    acc.x += f0.x * w; acc.y += f0.y * w;
    acc.z += f1.x * w; acc.w += f1.y * w;
}

__global__ void gather_agg_kernel(const __half* __restrict__ xw,
                                  const float* __restrict__ bias,
                                  float* __restrict__ xh) {
    int d = (blockIdx.x * blockDim.x + threadIdx.x) >> 5;
    int lane = threadIdx.x & 31;
    if (d >= NN) return;
    float di = g_dinv[d];
    float sw = di * di;
    float4 acc = make_float4(0.f, 0.f, 0.f, 0.f);
    {
        uint2 u = ((const uint2*)(xw + (size_t)d * FH))[lane];
        acc_half4(acc, u, sw);
    }
    int beg = g_rowstart[d], end = g_rowstart[d + 1];
    int i = beg;
    for (; i + 3 < end; i += 4) {                 // MLP=4
        int s0 = g_esrc[i], s1 = g_esrc[i + 1];
        int s2 = g_esrc[i + 2], s3 = g_esrc[i + 3];
        float w0 = g_ew2[i], w1 = g_ew2[i + 1];
        float w2 = g_ew2[i + 2], w3 = g_ew2[i + 3];
        uint2 u0 = ((const uint2*)(xw + (size_t)s0 * FH))[lane];
        uint2 u1 = ((const uint2*)(xw + (size_t)s1 * FH))[lane];
        uint2 u2 = ((const uint2*)(xw + (size_t)s2 * FH))[lane];
        uint2 u3 = ((const uint2*)(xw + (size_t)s3 * FH))[lane];
        acc_half4(acc, u0, w0);
        acc_half4(acc, u1, w1);
        acc_half4(acc, u2, w2);
        acc_half4(acc, u3, w3);
    }
    for (; i < end; i++) {
        int s = g_esrc[i];
        float w = g_ew2[i];
        uint2 u = ((const uint2*)(xw + (size_t)s * FH))[lane];
        acc_half4(acc, u, w);
    }
    float4 b = ((const float4*)bias)[lane];
    acc.x = fmaxf(acc.x + b.x, 0.f);
    acc.y = fmaxf(acc.y + b.y, 0.f);
    acc.z = fmaxf(acc.z + b.z, 0.f);
    acc.w = fmaxf(acc.w + b.w, 0.f);
    ((float4*)(xh + (size_t)d * FH))[lane] = acc;
}

// ---------------- shared MMA machinery (measured-good from R8) ------------
#define TS 132

__device__ __forceinline__ float to_tf32(float v) {
    uint32_t o;
    asm volatile("cvt.rna.tf32.f32 %0, %1;" : "=r"(o) : "f"(v));
    return __uint_as_float(o);
}

__device__ __forceinline__ void ldsm4(uint32_t* r, uint32_t addr) {
    asm volatile(
        "ldmatrix.sync.aligned.m8n8.x4.shared.b16 {%0,%1,%2,%3}, [%4];"
        : "=r"(r[0]), "=r"(r[1]), "=r"(r[2]), "=r"(r[3]) : "r"(addr));
}

__device__ __forceinline__ void mma_tf32(float* d, const uint32_t* a,
                                         uint32_t b0, uint32_t b1) {
    asm volatile(
        "mma.sync.aligned.m16n8k8.row.col.f32.tf32.tf32.f32 "
        "{%0,%1,%2,%3}, {%4,%5,%6,%7}, {%8,%9}, {%0,%1,%2,%3};\n"
        : "+f"(d[0]), "+f"(d[1]), "+f"(d[2]), "+f"(d[3])
        : "r"(a[0]), "r"(a[1]), "r"(a[2]), "r"(a[3]), "r"(b0), "r"(b1));
}

__device__ __forceinline__ void mma_pass(uint32_t aA0, uint32_t aA1,
                                         uint32_t bA0, uint32_t bA1,
                                         float acc[2][4][4]) {
    #pragma unroll
    for (int mi = 0; mi < 2; mi++)
        #pragma unroll
        for (int ni = 0; ni < 4; ni++)
            #pragma unroll
            for (int j = 0; j < 4; j++) acc[mi][ni][j] = 0.f;
    #pragma unroll
    for (int ks = 0; ks < 16; ks++) {
        uint32_t a0[4], a1[4], b01[4], b23[4];
        uint32_t ko = (uint32_t)ks * 32;
        ldsm4(a0,  aA0 + ko);
        ldsm4(a1,  aA1 + ko);
        ldsm4(b01, bA0 + ko);
        ldsm4(b23, bA1 + ko);
        mma_tf32(acc[0][0], a0, b01[0], b01[1]);
        mma_tf32(acc[0][1], a0, b01[2], b01[3]);
        mma_tf32(acc[0][2], a0, b23[0], b23[1]);
        mma_tf32(acc[0][3], a0, b23[2], b23[3]);
        mma_tf32(acc[1][0], a1, b01[0], b01[1]);
        mma_tf32(acc[1][1], a1, b01[2], b01[3]);
        mma_tf32(acc[1][2], a1, b23[0], b23[1]);
        mma_tf32(acc[1][3], a1, b23[2], b23[3]);
    }
}

__device__ __forceinline__ float sigm(float x) {
    return 1.f / (1.f + expf(-x));
}

// =====================================================================
// TF32 GEMM 64x64 tile, 256 threads, 3 CTAs/SM (measured-good from R14)
//   HALFOUT=true: C is __half* (fp16 output for the gather path)
// =====================================================================
#define G64_SMEM_BYTES (2 * 64 * TS * 4)   // 67584 B

template<bool BIAS, bool RELU, bool HALFOUT>
__global__ __launch_bounds__(256, 3)
void gemm64_tf32_kernel(const float* __restrict__ A,
                        const float* __restrict__ B,
                        const float* __restrict__ bias,
                        void* __restrict__ Cv,
                        int M, int Ncols) {
    extern __shared__ float smem[];
    float* As = smem;            // [64][TS]
    float* Bs = smem + 64 * TS;  // [64][TS]

    const int tid  = threadIdx.x;
    const int lane = tid & 31;
    const int wid  = tid >> 5;   // 0..7
    const int lr   = lane >> 2;
    const int lc   = lane & 3;
    const int bm = blockIdx.y * 64;
    const int bn = blockIdx.x * 64;

    #pragma unroll
    for (int it = 0; it < 8; it++) {
        int i = it * 256 + tid;
        int m = i >> 5;
        int q = (i & 31) << 2;
        int gr = bm + m;
        float4 v = make_float4(0.f, 0.f, 0.f, 0.f);
        if (gr < M) v = *(const float4*)(A + (size_t)gr * 128 + q);
        *(float4*)(As + m * TS + q) = make_float4(to_tf32(v.x), to_tf32(v.y),
                                                  to_tf32(v.z), to_tf32(v.w));
    }
    #pragma unroll
    for (int it = 0; it < 8; it++) {
        int i = it * 256 + tid;
        int k = i >> 4;
        int p = (i & 15) << 2;
        float4 v = *(const float4*)(B + (size_t)k * Ncols + bn + p);
        Bs[(p + 0) * TS + k] = to_tf32(v.x);
        Bs[(p + 1) * TS + k] = to_tf32(v.y);
        Bs[(p + 2) * TS + k] = to_tf32(v.z);
        Bs[(p + 3) * TS + k] = to_tf32(v.w);
    }
    __syncthreads();

    const int wtm = wid & 1;
    const int wtn = wid >> 1;
    uint32_t as_base = (uint32_t)__cvta_generic_to_shared(As);
    uint32_t bs_base = (uint32_t)__cvta_generic_to_shared(Bs);
    int arow = (lane & 7) + ((lane >> 3) & 1) * 8;
    int acol = (lane >> 4) << 2;
    int brow = (lane & 7) + ((lane >> 4) << 3);
    int bcol = ((lane >> 3) & 1) << 2;
    uint32_t aA0 = as_base + (((wtm * 32 +  0 + arow) * TS + acol) << 2);
    uint32_t aA1 = as_base + (((wtm * 32 + 16 + arow) * TS + acol) << 2);
    uint32_t bA0 = bs_base + (((wtn * 16 + brow) * TS + bcol) << 2);

    float acc[2][2][4];
    #pragma unroll
    for (int mi = 0; mi < 2; mi++)
        #pragma unroll
        for (int ni = 0; ni < 2; ni++)
            #pragma unroll
            for (int j = 0; j < 4; j++) acc[mi][ni][j] = 0.f;

    #pragma unroll
    for (int ks = 0; ks < 16; ks++) {
        uint32_t a0[4], a1[4], b01[4];
        uint32_t ko = (uint32_t)ks * 32;
        ldsm4(a0,  aA0 + ko);
        ldsm4(a1,  aA1 + ko);
        ldsm4(b01, bA0 + ko);
        mma_tf32(acc[0][0], a0, b01[0], b01[1]);
        mma_tf32(acc[0][1], a0, b01[2], b01[3]);
        mma_tf32(acc[1][0], a1, b01[0], b01[1]);
        mma_tf32(acc[1][1], a1, b01[2], b01[3]);
    }

    #pragma unroll
    for (int mi = 0; mi < 2; mi++) {
        int r0 = bm + wtm * 32 + mi * 16 + lr;
        int r1 = r0 + 8;
        #pragma unroll
        for (int ni = 0; ni < 2; ni++) {
            int c0 = bn + wtn * 16 + ni * 8 + (lc << 1);
            float b0 = 0.f, b1 = 0.f;
            if (BIAS) { b0 = bias[c0]; b1 = bias[c0 + 1]; }
            float v0 = acc[mi][ni][0] + b0;
            float v1 = acc[mi][ni][1] + b1;
            float v2 = acc[mi][ni][2] + b0;
            float v3 = acc[mi][ni][3] + b1;
            if (RELU) {
                v0 = fmaxf(v0, 0.f); v1 = fmaxf(v1, 0.f);
                v2 = fmaxf(v2, 0.f); v3 = fmaxf(v3, 0.f);
            }
            if (HALFOUT) {
                __half* Ch = (__half*)Cv;
                if (r0 < M)
                    *(__half2*)(Ch + (size_t)r0 * Ncols + c0) = __floats2half2_rn(v0, v1);
                if (r1 < M)
                    *(__half2*)(Ch + (size_t)r1 * Ncols + c0) = __floats2half2_rn(v2, v3);
            } else {
                float* C = (float*)Cv;
                if (r0 < M) *(float2*)(C + (size_t)r0 * Ncols + c0) = make_float2(v0, v1);
                if (r1 < M) *(float2*)(C + (size_t)r1 * Ncols + c0) = make_float2(v2, v3);
            }
        }
    }
}

// =====================================================================
// FUSED GRU (measured-good from R12). FC=true: final GRU — h' stays in
// smem, fc (h' @ fcW + fcB) computed in-kernel, writes `out` directly.
// =====================================================================
#define GRU_SMEM_BYTES (3 * 128 * TS * 4 + 2 * H3 * 4)   // 205824 B

__device__ __forceinline__ void load_w(float* Ws, const float* __restrict__ W,
                                       int tid) {
    #pragma unroll
    for (int it = 0; it < 8; it++) {
        int i = it * 512 + tid;
        int n = i >> 5;
        int q = (i & 31) << 2;
        float4 v = *(const float4*)(W + (size_t)n * 128 + q);
        *(float4*)(Ws + n * TS + q) = make_float4(to_tf32(v.x), to_tf32(v.y),
                                                  to_tf32(v.z), to_tf32(v.w));
    }
}

template<bool FC>
__global__ __launch_bounds__(512, 1)
void gru_fused_kernel(const float* __restrict__ xh,
                      const float* __restrict__ hin,
                      const float* __restrict__ Wih,
                      const float* __restrict__ Whh,
                      const float* __restrict__ bih,
                      const float* __restrict__ bhh,
                      float* __restrict__ hout,      // FC=false: h'; unused if FC
                      const float* __restrict__ fcW, // FC only
                      const float* __restrict__ fcB, // FC only
                      float* __restrict__ out,       // FC only
                      int M) {
    extern __shared__ float smem[];
    float* Axh = smem;
    float* Ah  = smem + 128 * TS;
    float* Ws  = smem + 256 * TS;
    float* bi_s = smem + 384 * TS;
    float* bh_s = bi_s + H3;

    const int tid  = threadIdx.x;
    const int lane = tid & 31;
    const int wid  = tid >> 5;
    const int lr   = lane >> 2;
    const int lc   = lane & 3;
    const int bm = blockIdx.x * 128;

    #pragma unroll
    for (int it = 0; it < 8; it++) {
        int i = it * 512 + tid;
        int m = i >> 5;
        int q = (i & 31) << 2;
        int gr = bm + m;
        float4 vx = make_float4(0.f, 0.f, 0.f, 0.f);
        float4 vh = make_float4(0.f, 0.f, 0.f, 0.f);
        if (gr < M) {
            vx = *(const float4*)(xh  + (size_t)gr * 128 + q);
            vh = *(const float4*)(hin + (size_t)gr * 128 + q);
        }
        *(float4*)(Axh + m * TS + q) = make_float4(to_tf32(vx.x), to_tf32(vx.y),
                                                   to_tf32(vx.z), to_tf32(vx.w));
        *(float4*)(Ah + m * TS + q) = vh;
    }
    if (tid < H3) { bi_s[tid] = bih[tid]; bh_s[tid] = bhh[tid]; }

    const int wtm = wid & 3;
    const int wtn = wid >> 2;
    int arow = (lane & 7) + ((lane >> 3) & 1) * 8;
    int acol = (lane >> 4) << 2;
    int brow = (lane & 7) + ((lane >> 4) << 3);
    int bcol = ((lane >> 3) & 1) << 2;
    uint32_t axh_b = (uint32_t)__cvta_generic_to_shared(Axh);
    uint32_t ah_b  = (uint32_t)__cvta_generic_to_shared(Ah);
    uint32_t ws_b  = (uint32_t)__cvta_generic_to_shared(Ws);
    uint32_t aO0 = ((wtm * 32 +  0 + arow) * TS + acol) << 2;
    uint32_t aO1 = ((wtm * 32 + 16 + arow) * TS + acol) << 2;
    uint32_t bO0 = ((wtn * 32 +  0 + brow) * TS + bcol) << 2;
    uint32_t bO1 = ((wtn * 32 + 16 + brow) * TS + bcol) << 2;

    float gi[2][4][4], gh[2][4][4], ra[2][4][4], na[2][4][4];

    // ======== gate r (slice 0) ========
    load_w(Ws, Wih, tid);
    __syncthreads();
    mma_pass(axh_b + aO0, axh_b + aO1, ws_b + bO0, ws_b + bO1, gi);
    __syncthreads();
    load_w(Ws, Whh, tid);
    __syncthreads();
    mma_pass(ah_b + aO0, ah_b + aO1, ws_b + bO0, ws_b + bO1, gh);
    #pragma unroll
    for (int mi = 0; mi < 2; mi++)
        #pragma unroll
        for (int ni = 0; ni < 4; ni++) {
            int col = wtn * 32 + ni * 8 + (lc << 1);
            float bs0 = bi_s[col] + bh_s[col];
            float bs1 = bi_s[col + 1] + bh_s[col + 1];
            ra[mi][ni][0] = sigm(gi[mi][ni][0] + gh[mi][ni][0] + bs0);
            ra[mi][ni][1] = sigm(gi[mi][ni][1] + gh[mi][ni][1] + bs1);
            ra[mi][ni][2] = sigm(gi[mi][ni][2] + gh[mi][ni][2] + bs0);
            ra[mi][ni][3] = sigm(gi[mi][ni][3] + gh[mi][ni][3] + bs1);
        }

    // ======== gate n (slice 2) ========
    __syncthreads();
    load_w(Ws, Wih + 2 * 128 * 128, tid);
    __syncthreads();
    mma_pass(axh_b + aO0, axh_b + aO1, ws_b + bO0, ws_b + bO1, gi);
    __syncthreads();
    load_w(Ws, Whh + 2 * 128 * 128, tid);
    __syncthreads();
    mma_pass(ah_b + aO0, ah_b + aO1, ws_b + bO0, ws_b + bO1, gh);
    #pragma unroll
    for (int mi = 0; mi < 2; mi++)
        #pragma unroll
        for (int ni = 0; ni < 4; ni++) {
            int col = wtn * 32 + ni * 8 + (lc << 1);
            float bi0 = bi_s[256 + col], bi1 = bi_s[256 + col + 1];
            float bh0 = bh_s[256 + col], bh1 = bh_s[256 + col + 1];
            na[mi][ni][0] = tanhf(gi[mi][ni][0] + bi0 + ra[mi][ni][0] * (gh[mi][ni][0] + bh0));
            na[mi][ni][1] = tanhf(gi[mi][ni][1] + bi1 + ra[mi][ni][1] * (gh[mi][ni][1] + bh1));
            na[mi][ni][2] = tanhf(gi[mi][ni][2] + bi0 + ra[mi][ni][2] * (gh[mi][ni][2] + bh0));
            na[mi][ni][3] = tanhf(gi[mi][ni][3] + bi1 + ra[mi][ni][3] * (gh[mi][ni][3] + bh1));
        }

    // ======== gate z (slice 1) + blend ========
    __syncthreads();
    load_w(Ws, Wih + 128 * 128, tid);
    __syncthreads();
    mma_pass(axh_b + aO0, axh_b + aO1, ws_b + bO0, ws_b + bO1, gi);
    __syncthreads();
    load_w(Ws, Whh + 128 * 128, tid);
    __syncthreads();
    mma_pass(ah_b + aO0, ah_b + aO1, ws_b + bO0, ws_b + bO1, gh);
    #pragma unroll
    for (int mi = 0; mi < 2; mi++) {
        int row0 = wtm * 32 + mi * 16 + lr;
        int row1 = row0 + 8;
        int gr0 = bm + row0, gr1 = bm + row1;
        #pragma unroll
        for (int ni = 0; ni < 4; ni++) {
            int col = wtn * 32 + ni * 8 + (lc << 1);
            float bs0 = bi_s[128 + col] + bh_s[128 + col];
            float bs1 = bi_s[128 + col + 1] + bh_s[128 + col + 1];
            float z0 = sigm(gi[mi][ni][0] + gh[mi][ni][0] + bs0);
            float z1 = sigm(gi[mi][ni][1] + gh[mi][ni][1] + bs1);
            float z2 = sigm(gi[mi][ni][2] + gh[mi][ni][2] + bs0);
            float z3 = sigm(gi[mi][ni][3] + gh[mi][ni][3] + bs1);
            float2 h0v = *(float2*)(Ah + row0 * TS + col);
            float2 h1v = *(float2*)(Ah + row1 * TS + col);
            float v0 = (1.f - z0) * na[mi][ni][0] + z0 * h0v.x;
            float v1 = (1.f - z1) * na[mi][ni][1] + z1 * h0v.y;
            float v2 = (1.f - z2) * na[mi][ni][2] + z2 * h1v.x;
            float v3 = (1.f - z3) * na[mi][ni][3] + z3 * h1v.y;
            if (!FC) {
                if (gr0 < M) *(float2*)(hout + (size_t)gr0 * 128 + col) = make_float2(v0, v1);
                if (gr1 < M) *(float2*)(hout + (size_t)gr1 * 128 + col) = make_float2(v2, v3);
            } else {
                // stash h' (tf32) in Axh for the in-kernel fc matmul
                Axh[row0 * TS + col]     = to_tf32(v0);
                Axh[row0 * TS + col + 1] = to_tf32(v1);
                Axh[row1 * TS + col]     = to_tf32(v2);
                Axh[row1 * TS + col + 1] = to_tf32(v3);
            }
        }
    }

    if (FC) {
        __syncthreads();   // all h' in Axh; Ws no longer read
        // load fcW^T into Ws: Ws[n][k] = fcW[k][n], n padded 40->64
        #pragma unroll
        for (int it = 0; it < 16; it++) {
            int i = it * 512 + tid;    // 8192 = 64 x 128
            int n = i >> 7;
            int k = i & 127;
            float v = (n < CC) ? fcW[(size_t)k * CC + n] : 0.f;
            Ws[n * TS + k] = to_tf32(v);
        }
        __syncthreads();

        uint32_t bF = ws_b + (((wtn * 16 + brow) * TS + bcol) << 2);
        float fa[2][2][4];
        #pragma unroll
        for (int mi = 0; mi < 2; mi++)
            #pragma unroll
            for (int ni = 0; ni < 2; ni++)
                #pragma unroll
                for (int j = 0; j < 4; j++) fa[mi][ni][j] = 0.f;
        #pragma unroll
        for (int ks = 0; ks < 16; ks++) {
            uint32_t a0[4], a1[4], b01[4];
            uint32_t ko = (uint32_t)ks * 32;
            ldsm4(a0,  axh_b + aO0 + ko);
            ldsm4(a1,  axh_b + aO1 + ko);
            ldsm4(b01, bF + ko);
            mma_tf32(fa[0][0], a0, b01[0], b01[1]);
            mma_tf32(fa[0][1], a0, b01[2], b01[3]);
            mma_tf32(fa[1][0], a1, b01[0], b01[1]);
            mma_tf32(fa[1][1], a1, b01[2], b01[3]);
        }
        #pragma unroll
        for (int mi = 0; mi < 2; mi++) {
            int r0 = bm + wtm * 32 + mi * 16 + lr;
            int r1 = r0 + 8;
            #pragma unroll
            for (int ni = 0; ni < 2; ni++) {
                int c0 = wtn * 16 + ni * 8 + (lc << 1);
                if (c0 >= CC) continue;
                float b0 = fcB[c0];
                float b1 = (c0 + 1 < CC) ? fcB[c0 + 1] : 0.f;
                if (r0 < M) {
                    out[(size_t)r0 * CC + c0] = fa[mi][ni][0] + b0;
                    if (c0 + 1 < CC) out[(size_t)r0 * CC + c0 + 1] = fa[mi][ni][1] + b1;
                }
                if (r1 < M) {
                    out[(size_t)r1 * CC + c0] = fa[mi][ni][2] + b0;
                    if (c0 + 1 < CC) out[(size_t)r1 * CC + c0 + 1] = fa[mi][ni][3] + b1;
                }
            }
        }
    }
}

// ---------------- host orchestration: 2-stream overlap ----------------
extern "C" void kernel_launch(void* const* d_in, const int* in_sizes, int n_in,
                              void* d_out, int out_size) {
    const float* x     = (const float*)d_in[0];
    const int*   ei    = (const int*)  d_in[1];
    const float* ew    = (const float*)d_in[2];
    const float* h0    = (const float*)d_in[3];
    const float* linW  = (const float*)d_in[4];
    const float* linB  = (const float*)d_in[5];
    const float* convW = (const float*)d_in[6];
    const float* convB = (const float*)d_in[7];
    const float* Wih   = (const float*)d_in[8];
    const float* Whh   = (const float*)d_in[9];
    const float* bih   = (const float*)d_in[10];
    const float* bhh   = (const float*)d_in[11];
    const float* fcW   = (const float*)d_in[12];
    const float* fcB   = (const float*)d_in[13];
    float* out = (float*)d_out;

    const int* src = ei;
    const int* dst = ei + EE;

    static cudaStream_t s2 = nullptr;
    static cudaEvent_t evFork, evG0, evGru0, evA0, evR0, evA1, evA2, evEnd;
    static bool s_init_done = false;
    if (!s_init_done) {
        cudaFuncSetAttribute(gemm64_tf32_kernel<true, true, false>,
                             cudaFuncAttributeMaxDynamicSharedMemorySize, G64_SMEM_BYTES);
        cudaFuncSetAttribute(gemm64_tf32_kernel<false, false, true>,
                             cudaFuncAttributeMaxDynamicSharedMemorySize, G64_SMEM_BYTES);
        cudaFuncSetAttribute(gru_fused_kernel<false>,
                             cudaFuncAttributeMaxDynamicSharedMemorySize, GRU_SMEM_BYTES);
        cudaFuncSetAttribute(gru_fused_kernel<true>,
                             cudaFuncAttributeMaxDynamicSharedMemorySize, GRU_SMEM_BYTES);
        cudaStreamCreateWithFlags(&s2, cudaStreamNonBlocking);
        cudaEventCreateWithFlags(&evFork, cudaEventDisableTiming);
        cudaEventCreateWithFlags(&evG0,   cudaEventDisableTiming);
        cudaEventCreateWithFlags(&evGru0, cudaEventDisableTiming);
        cudaEventCreateWithFlags(&evA0,   cudaEventDisableTiming);
        cudaEventCreateWithFlags(&evR0,   cudaEventDisableTiming);
        cudaEventCreateWithFlags(&evA1,   cudaEventDisableTiming);
        cudaEventCreateWithFlags(&evA2,   cudaEventDisableTiming);
        cudaEventCreateWithFlags(&evEnd,  cudaEventDisableTiming);
        s_init_done = true;
    }

    float *p_xh1, *p_xh2, *p_h;
    __half* p_xwh;
    cudaGetSymbolAddress((void**)&p_xh1, g_xh1);
    cudaGetSymbolAddress((void**)&p_xh2, g_xh2);
    cudaGetSymbolAddress((void**)&p_xwh, g_xwh);
    cudaGetSymbolAddress((void**)&p_h,   g_h);

    const int EB = 256;
    const int NB = (NN + 127) / 128;       // 782
    const int NB64 = (NN + 63) / 64;       // 1563
    const dim3 blk256(256);
    const dim3 blk512(512);
    const dim3 g64_128(2, NB64);
    const int gatherBlocks = (NN * 32 + 255) / 256;

    const float* W0 = convW;
    const float* W1 = convW + (size_t)1 * FH * FH;
    const float* W2 = convW + (size_t)2 * FH * FH;
    const float* b0 = convB;
    const float* b1 = convB + FH;
    const float* b2 = convB + 2 * FH;

    // ---- fork: s2 branches off the capturing (legacy) stream ----
    cudaEventRecord(evFork, 0);
    cudaStreamWaitEvent(s2, evFork, 0);

    // ---- s2: lin -> G_0 -> GRU0 ----
    gemm64_tf32_kernel<true, true, false><<<g64_128, blk256, G64_SMEM_BYTES, s2>>>(
        x, linW, linB, p_xh1, NN, FH);
    gemm64_tf32_kernel<false, false, true><<<g64_128, blk256, G64_SMEM_BYTES, s2>>>(
        p_xh1, W0, nullptr, p_xwh, NN, FH);
    cudaEventRecord(evG0, s2);
    gru_fused_kernel<false><<<NB, blk512, GRU_SMEM_BYTES, s2>>>(
        p_xh1, h0, Wih, Whh, bih, bhh, p_h, nullptr, nullptr, nullptr, NN);
    cudaEventRecord(evGru0, s2);

    // ---- s0: CSR build (concurrent with lin/G_0/GRU0) ----
    init_deg_kernel<<<(NN + 255) / 256, 256>>>();
    accum_deg_kernel<<<(EE + EB - 1) / EB, EB>>>(dst, ew);
    scan1_kernel<<<NBLK, SCAN_B>>>();
    scan2_kernel<<<1, 256>>>();
    scan3_kernel<<<(NN + 255) / 256, 256>>>();
    fill_kernel<<<(EE + EB - 1) / EB, EB>>>(src, dst, ew);

    // ---- s0: A_0 (needs CSR + G_0) ----
    cudaStreamWaitEvent(0, evG0, 0);
    gather_agg_kernel<<<gatherBlocks, 256>>>(p_xwh, b0, p_xh2);
    cudaEventRecord(evA0, 0);

    // ---- s2: R_0 (needs A_0 + GRU0[in-order]) ----
    cudaStreamWaitEvent(s2, evA0, 0);
    gru_fused_kernel<false><<<NB, blk512, GRU_SMEM_BYTES, s2>>>(
        p_xh2, p_h, Wih, Whh, bih, bhh, p_h, nullptr, nullptr, nullptr, NN);
    cudaEventRecord(evR0, s2);

    // ---- s0: G_1 -> A_1 (A_1 writes xh1: wait GRU0 reader) ----
    gemm64_tf32_kernel<false, false, true><<<g64_128, blk256, G64_SMEM_BYTES>>>(
        p_xh2, W1, nullptr, p_xwh, NN, FH);
    cudaStreamWaitEvent(0, evGru0, 0);
    gather_agg_kernel<<<gatherBlocks, 256>>>(p_xwh, b1, p_xh1);
    cudaEventRecord(evA1, 0);

    // ---- s2: R_1 (needs A_1 + R_0[in-order]) ----
    cudaStreamWaitEvent(s2, evA1, 0);
    gru_fused_kernel<false><<<NB, blk512, GRU_SMEM_BYTES, s2>>>(
        p_xh1, p_h, Wih, Whh, bih, bhh, p_h, nullptr, nullptr, nullptr, NN);

    // ---- s0: G_2 -> A_2 (A_2 writes xh2: wait R_0 reader) ----
    gemm64_tf32_kernel<false, false, true><<<g64_128, blk256, G64_SMEM_BYTES>>>(
        p_xh1, W2, nullptr, p_xwh, NN, FH);
    cudaStreamWaitEvent(0, evR0, 0);
    gather_agg_kernel<<<gatherBlocks, 256>>>(p_xwh, b2, p_xh2);
    cudaEventRecord(evA2, 0);

    // ---- s2: R_2 with fused fc -> writes out directly ----
    cudaStreamWaitEvent(s2, evA2, 0);
    gru_fused_kernel<true><<<NB, blk512, GRU_SMEM_BYTES, s2>>>(
        p_xh2, p_h, Wih, Whh, bih, bhh, nullptr, fcW, fcB, out, NN);
    cudaEventRecord(evEnd, s2);

    // ---- join back to the capturing stream ----
    cudaStreamWaitEvent(0, evEnd, 0);
}